// round 11
// baseline (speedup 1.0000x reference)
#include <cuda_runtime.h>
#include <cstdint>

// ---------------------------------------------------------------------------
// DilatedReparamBlock fused: merge 7 BN(dwconv) branches into one exact 13x13
// depthwise conv + bias, then one packed-fp32 (fma.rn.f32x2) conv.
// R11 = R9 three-pass ping-pong kernel, rethreaded: 256 threads/block =
//       4 images x 64 threads (56 active + 8 idle lanes) so every warp is
//       image-pure and the SM runs 16 warps (512 thr x 128 regs = full RF).
// x: [16, 384, 56, 56] fp32 -> out same shape.
// ---------------------------------------------------------------------------

#define C_CH 384
#define NB 16
#define HW 56
#define PAD 6
#define PH 68                  // padded row stride (272B: 16B-aligned rows)
#define IMG_PER_BLK 4
#define THREADS 256            // 4 images * 64 threads (56 active + 8 idle)
#define WSTRIDE 14             // u64 taps per weight row (112B, 16B aligned)
#define W_U64_PER_IMG (13 * WSTRIDE)                   // 182
#define SMEM_IN_BYTES (IMG_PER_BLK * PH * PH * 4)      // 73984
#define SMEM_W_BYTES  (IMG_PER_BLK * W_U64_PER_IMG * 8)// 5824
#define SMEM_BYTES    (SMEM_IN_BYTES + SMEM_W_BYTES)   // 79808

typedef unsigned long long u64;

// Merged weights: per channel, 13 rows x WSTRIDE u64; entry j (j<13) is the
// tap value DUPLICATED (w,w) so it is a ready FFMA2 b-operand.
__device__ u64 g_Wd[C_CH * W_U64_PER_IMG];
__device__ float g_bias[C_CH];

// ---------------------------------------------------------------------------
// Kernel 1: fold the 7 BN(dwconv) branches into one 13x13 kernel + bias.
// ---------------------------------------------------------------------------
__global__ void merge_kernel(const float* __restrict__ w_lk,
                             const float* __restrict__ w_b0,
                             const float* __restrict__ w_b1,
                             const float* __restrict__ w_b2,
                             const float* __restrict__ w_b3,
                             const float* __restrict__ w_b4,
                             const float* __restrict__ w_b5,
                             const float* __restrict__ gamma,
                             const float* __restrict__ beta,
                             const float* __restrict__ mean,
                             const float* __restrict__ var) {
    int c = blockIdx.x;
    int t = threadIdx.x;

    float inv[7];
#pragma unroll
    for (int m = 0; m < 7; m++)
        inv[m] = gamma[m * C_CH + c] * rsqrtf(var[m * C_CH + c] + 1e-5f);

    if (t < 169) {
        int i = t / 13, j = t % 13;
        float val = inv[0] * w_lk[c * 169 + t];

        const float* ws[6] = {w_b0, w_b1, w_b2, w_b3, w_b4, w_b5};
        const int ks[6] = {5, 7, 7, 3, 3, 3};
        const int rs[6] = {1, 1, 2, 3, 4, 5};
#pragma unroll
        for (int b = 0; b < 6; b++) {
            int k = ks[b], r = rs[b];
            int span = r * (k - 1) + 1;
            int off = (13 - span) / 2;           // center the dilated kernel
            int ai = i - off, aj = j - off;
            if (ai >= 0 && aj >= 0 && (ai % r) == 0 && (aj % r) == 0) {
                int a = ai / r, bb = aj / r;
                if (a < k && bb < k)
                    val += inv[b + 1] * ws[b][c * k * k + a * k + bb];
            }
        }
        float2 d2 = make_float2(val, val);
        g_Wd[c * W_U64_PER_IMG + i * WSTRIDE + j] =
            *reinterpret_cast<u64*>(&d2);
    } else if (t < 169 + 13) {
        // zero pad tap 13 of each weight row (WSTRIDE=14)
        int i = t - 169;
        g_Wd[c * W_U64_PER_IMG + i * WSTRIDE + 13] = 0ull;
    }
    if (t == 0) {
        float bsum = 0.f;
#pragma unroll
        for (int m = 0; m < 7; m++)
            bsum += beta[m * C_CH + c] - mean[m * C_CH + c] * inv[m];
        g_bias[c] = bsum;
    }
}

// ---------------------------------------------------------------------------
// Packed fp32 helpers. FFMA2 itself must be asm (PTX-only on sm_103a), but
// operand packing is compiler-visible so aligned pairs cost ZERO instructions.
// ---------------------------------------------------------------------------
__device__ __forceinline__ u64 pack2(float lo, float hi) {
    float2 tv = make_float2(lo, hi);
    return *reinterpret_cast<u64*>(&tv);
}
__device__ __forceinline__ void fma2(u64& a, u64 x, u64 w) {
    asm("fma.rn.f32x2 %0, %1, %2, %0;" : "+l"(a) : "l"(x), "l"(w));
}

__device__ __forceinline__ void load5(float4* f, const float* rowptr) {
    const float4* rp = reinterpret_cast<const float4*>(rowptr);
#pragma unroll
    for (int k = 0; k < 5; k++) f[k] = rp[k];       // 5x LDS.128
}

// component i (0..19) of the 5-float4 row buffer
__device__ __forceinline__ float comp(const float4* f, int i) {
    const float4& v = f[i >> 2];
    switch (i & 3) {
        case 0: return v.x;
        case 1: return v.y;
        case 2: return v.z;
        default: return v.w;
    }
}

// ---------------------------------------------------------------------------
// Pack one (already loaded) input row and fan out to NA accumulator rows.
// acc[a] uses weight row (wrow0 - a). Caller guarantees rows in range.
// Even pairs are free (aligned halves of the LDS.128 results).
// ---------------------------------------------------------------------------
template <int NA>
__device__ __forceinline__ void compute_row(const float4* __restrict__ f,
                                            const u64* __restrict__ mw,
                                            int wrow0,
                                            u64 (*acc)[4]) {
    u64 p[19];
#pragma unroll
    for (int k = 0; k < 5; k++) {                   // even pairs: zero-cost
        p[4 * k] = *reinterpret_cast<const u64*>(&f[k].x);
        if (4 * k + 2 < 19)
            p[4 * k + 2] = *reinterpret_cast<const u64*>(&f[k].z);
    }
#pragma unroll
    for (int k = 0; k < 9; k++)                     // odd pairs: 2 movs each
        p[2 * k + 1] = pack2(comp(f, 2 * k + 1), comp(f, 2 * k + 2));

#pragma unroll
    for (int a = 0; a < NA; a++) {
        const u64* wr = mw + (wrow0 - a) * WSTRIDE;
        const ulonglong2* wr2 = reinterpret_cast<const ulonglong2*>(wr);
#pragma unroll
        for (int jj = 0; jj < 6; jj++) {            // taps 2jj, 2jj+1
            ulonglong2 wv = wr2[jj];                // LDS.128 (broadcast)
            fma2(acc[a][0], p[2 * jj],     wv.x);
            fma2(acc[a][1], p[2 * jj + 2], wv.x);
            fma2(acc[a][2], p[2 * jj + 4], wv.x);
            fma2(acc[a][3], p[2 * jj + 6], wv.x);
            fma2(acc[a][0], p[2 * jj + 1], wv.y);
            fma2(acc[a][1], p[2 * jj + 3], wv.y);
            fma2(acc[a][2], p[2 * jj + 5], wv.y);
            fma2(acc[a][3], p[2 * jj + 7], wv.y);
        }
        u64 w12 = wr[12];                           // tap 12 (LDS.64)
        fma2(acc[a][0], p[12], w12);
        fma2(acc[a][1], p[14], w12);
        fma2(acc[a][2], p[16], w12);
        fma2(acc[a][3], p[18], w12);
    }
}

template <int NA>
__device__ __forceinline__ void proc_row(const float* __restrict__ rowptr,
                                         const u64* __restrict__ mw,
                                         int wrow0,
                                         u64 (*acc)[4]) {
    float4 f[5];
    load5(f, rowptr);
    compute_row<NA>(f, mw, wrow0, acc);
}

__device__ __forceinline__ void store_rows(float* obase, int y0, int dfirst,
                                           int nd, const u64 (*acc)[4]) {
    for (int d = 0; d < nd; d++) {
        ulonglong2* orow = reinterpret_cast<ulonglong2*>(
            obase + (y0 + dfirst + d) * HW);         // +x0 folded by caller
        orow[0] = make_ulonglong2(acc[d][0], acc[d][1]);
        orow[1] = make_ulonglong2(acc[d][2], acc[d][3]);
    }
}

// ---------------------------------------------------------------------------
// Kernel 2: depthwise 13x13 conv + bias.
// Block = 4 (n,c) images x 64 threads each; per image lanes 0..55 compute
// (7 x-tiles of 8 wide x 8 y-tiles of 7 rows), lanes 56..63 idle. Every warp
// is image-pure; 2 blocks x 256 thr x 128 regs fills the register file ->
// 16 warps/SM for latency hiding.
// Three passes (d=0-1, 2-3, 4-6); steady loops: unroll 1 + ping-pong.
// ---------------------------------------------------------------------------
extern __shared__ char s_raw[];

__global__ __launch_bounds__(THREADS, 2)
void conv13_kernel(const float* __restrict__ x, float* __restrict__ out) {
    float* s_in = reinterpret_cast<float*>(s_raw);
    u64* s_w = reinterpret_cast<u64*>(s_raw + SMEM_IN_BYTES);

    int t = threadIdx.x;
    int img_l = t >> 6;         // image slot 0..3  (64 threads each)
    int s = t & 63;             // lane within image; 56..63 idle
    bool active = (s < 56);
    int tx = s % 7, ty = s / 7; // valid only when active
    int x0 = tx * 8;
    int y0 = ty * 7;

    int img = blockIdx.x * IMG_PER_BLK + img_l;   // flat (n*C + c)
    int c = img % C_CH;

    float* my = s_in + img_l * (PH * PH);
    u64* mw = s_w + img_l * W_U64_PER_IMG;
    const float* gx = x + (size_t)img * (HW * HW);

    // Stage merged weights: 182 u64 = 91 ulonglong2 per image (guarded).
    if (active) {
        const ulonglong2* src =
            reinterpret_cast<const ulonglong2*>(g_Wd + (size_t)c * W_U64_PER_IMG);
        ulonglong2* dst = reinterpret_cast<ulonglong2*>(mw);
        for (int k = s; k < W_U64_PER_IMG / 2; k += 56)
            dst[k] = __ldg(src + k);

        // Stage input: vector zero-fill padded tile.
        float4* z = reinterpret_cast<float4*>(my);
        for (int k = s; k < (PH * PH) / 4; k += 56)        // 1156 float4
            z[k] = make_float4(0.f, 0.f, 0.f, 0.f);
    }
    __syncthreads();
    if (active) {
        // Coalesced float2 interior copy (constant-divisor indexing).
        int col2 = s % 28;          // column pair 0..27
        int r0 = s / 28;            // 0 or 1
        const float2* g2 = reinterpret_cast<const float2*>(gx);
#pragma unroll
        for (int k = 0; k < 28; k++) {
            int r = r0 + 2 * k;
            float2 v = __ldg(g2 + r * 28 + col2);
            *reinterpret_cast<float2*>(my + (r + PAD) * PH + PAD + 2 * col2) = v;
        }
    }
    __syncthreads();

    if (!active) return;

    float bb = __ldg(&g_bias[c]);
    u64 bias2 = pack2(bb, bb);

    const float* rbase = my + y0 * PH + x0;   // padded coords, 16B aligned
    float* obase = out + (size_t)img * (HW * HW) + x0;

    // =================== Pass 1: output rows d = 0..1 (rows 0..13) ==========
    {
        u64 acc[2][4];
#pragma unroll
        for (int a = 0; a < 2; a++)
#pragma unroll
            for (int q = 0; q < 4; q++) acc[a][q] = bias2;

        proc_row<1>(rbase + 0 * PH, mw, 0, &acc[0]);   // ir=0: d0 only
        float4 f[5], g[5];
        load5(f, rbase + 1 * PH);
#pragma unroll 1
        for (int ir = 1; ir < 12; ir += 2) {           // bodies: 1..12
            load5(g, rbase + (ir + 1) * PH);
            compute_row<2>(f, mw, ir, &acc[0]);
            load5(f, rbase + (ir + 2) * PH);           // last: row 13
            compute_row<2>(g, mw, ir + 1, &acc[0]);
        }
        compute_row<1>(f, mw, 12, &acc[1]);            // ir=13: d1 only
        store_rows(obase, y0, 0, 2, acc);
    }

    // =================== Pass 2: output rows d = 2..3 (rows 2..15) ==========
    {
        u64 acc[2][4];
#pragma unroll
        for (int a = 0; a < 2; a++)
#pragma unroll
            for (int q = 0; q < 4; q++) acc[a][q] = bias2;

        proc_row<1>(rbase + 2 * PH, mw, 0, &acc[0]);   // ir=2: d2 only
        float4 f[5], g[5];
        load5(f, rbase + 3 * PH);
#pragma unroll 1
        for (int ir = 3; ir < 14; ir += 2) {           // bodies: 3..14
            load5(g, rbase + (ir + 1) * PH);
            compute_row<2>(f, mw, ir - 2, &acc[0]);
            load5(f, rbase + (ir + 2) * PH);           // last: row 15
            compute_row<2>(g, mw, ir - 1, &acc[0]);
        }
        compute_row<1>(f, mw, 12, &acc[1]);            // ir=15: d3 only
        store_rows(obase, y0, 2, 2, acc);
    }

    // =================== Pass 3: output rows d = 4..6 (rows 4..18) ==========
    {
        u64 acc[3][4];
#pragma unroll
        for (int a = 0; a < 3; a++)
#pragma unroll
            for (int q = 0; q < 4; q++) acc[a][q] = bias2;

        proc_row<1>(rbase + 4 * PH, mw, 0, &acc[0]);   // ir=4: d4
        proc_row<2>(rbase + 5 * PH, mw, 1, &acc[0]);   // ir=5: d4,d5
        float4 f[5], g[5];
        load5(f, rbase + 6 * PH);
#pragma unroll 1
        for (int ir = 6; ir < 15; ir += 2) {           // bodies: 6..15
            load5(g, rbase + (ir + 1) * PH);
            compute_row<3>(f, mw, ir - 4, &acc[0]);
            load5(f, rbase + (ir + 2) * PH);           // last: row 16
            compute_row<3>(g, mw, ir - 3, &acc[0]);
        }
        compute_row<3>(f, mw, 12, &acc[0]);            // ir=16: d4,d5,d6
        proc_row<2>(rbase + 17 * PH, mw, 12, &acc[1]); // ir=17: d5,d6
        proc_row<1>(rbase + 18 * PH, mw, 12, &acc[2]); // ir=18: d6
        store_rows(obase, y0, 4, 3, acc);
    }
}

// ---------------------------------------------------------------------------
extern "C" void kernel_launch(void* const* d_in, const int* in_sizes, int n_in,
                              void* d_out, int out_size) {
    const float* x    = (const float*)d_in[0];
    const float* w_lk = (const float*)d_in[1];
    const float* w_b0 = (const float*)d_in[2];
    const float* w_b1 = (const float*)d_in[3];
    const float* w_b2 = (const float*)d_in[4];
    const float* w_b3 = (const float*)d_in[5];
    const float* w_b4 = (const float*)d_in[6];
    const float* w_b5 = (const float*)d_in[7];
    const float* gam  = (const float*)d_in[8];
    const float* bet  = (const float*)d_in[9];
    const float* mea  = (const float*)d_in[10];
    const float* var  = (const float*)d_in[11];
    float* out = (float*)d_out;

    merge_kernel<<<C_CH, 224>>>(w_lk, w_b0, w_b1, w_b2, w_b3, w_b4, w_b5,
                                gam, bet, mea, var);

    cudaFuncSetAttribute(conv13_kernel,
                         cudaFuncAttributeMaxDynamicSharedMemorySize,
                         SMEM_BYTES);
    int grid = (NB * C_CH) / IMG_PER_BLK;  // 1536
    conv13_kernel<<<grid, THREADS, SMEM_BYTES>>>(x, out);
}

// round 12
// speedup vs baseline: 1.3435x; 1.3435x over previous
#include <cuda_runtime.h>
#include <cstdint>

// ---------------------------------------------------------------------------
// DilatedReparamBlock fused: merge 7 BN(dwconv) branches into one exact 13x13
// depthwise conv + bias, then one packed-fp32 (fma.rn.f32x2) conv.
// R12: even/odd-lane FFMA2 formulation. Each output's accumulator holds
// (even-tap partial, odd-tap partial); ALL input pairs are aligned float2
// registers straight from LDS.64 -> zero packing instructions. Weight pairs
// (wpE/wpO) prebuilt by the merge kernel. 3 passes + ping-pong prefetch.
// x: [16, 384, 56, 56] fp32 -> out same shape.
// ---------------------------------------------------------------------------

#define C_CH 384
#define NB 16
#define HW 56
#define PAD 6
#define PH 68                  // padded row stride (272B; rows 16B-aligned)
#define IMG_PER_BLK 4
#define THREADS 224            // 4 images * 56 threads (7 x-tiles * 8 y-tiles)
#define WSTRIDE 16             // u64 per weight row: [wpE 0..6, pad, wpO 0..6, pad]
#define W_U64_PER_IMG (13 * WSTRIDE)                   // 208
#define SMEM_IN_BYTES (IMG_PER_BLK * PH * PH * 4)      // 73984
#define SMEM_W_BYTES  (IMG_PER_BLK * W_U64_PER_IMG * 8)// 6656
#define SMEM_BYTES    (SMEM_IN_BYTES + SMEM_W_BYTES)   // 80640

typedef unsigned long long u64;

// Merged weight PAIRS per channel/row: wpE[k]=(w2k,w2k+1) k=0..5, wpE[6]=(w12,0)
// at u64 slots 0..6; wpO[0]=(0,w0), wpO[k]=(w2k-1,w2k) k=1..6 at slots 8..14.
__device__ u64 g_Wd[C_CH * W_U64_PER_IMG];
__device__ float g_bias[C_CH];

// ---------------------------------------------------------------------------
// Kernel 1: fold the 7 BN(dwconv) branches into one 13x13 kernel + bias,
// then emit the even/odd weight-pair layout.
// ---------------------------------------------------------------------------
__global__ void merge_kernel(const float* __restrict__ w_lk,
                             const float* __restrict__ w_b0,
                             const float* __restrict__ w_b1,
                             const float* __restrict__ w_b2,
                             const float* __restrict__ w_b3,
                             const float* __restrict__ w_b4,
                             const float* __restrict__ w_b5,
                             const float* __restrict__ gamma,
                             const float* __restrict__ beta,
                             const float* __restrict__ mean,
                             const float* __restrict__ var) {
    __shared__ float v[169];
    int c = blockIdx.x;
    int t = threadIdx.x;

    float inv[7];
#pragma unroll
    for (int m = 0; m < 7; m++)
        inv[m] = gamma[m * C_CH + c] * rsqrtf(var[m * C_CH + c] + 1e-5f);

    if (t < 169) {
        int i = t / 13, j = t % 13;
        float val = inv[0] * w_lk[c * 169 + t];

        const float* ws[6] = {w_b0, w_b1, w_b2, w_b3, w_b4, w_b5};
        const int ks[6] = {5, 7, 7, 3, 3, 3};
        const int rs[6] = {1, 1, 2, 3, 4, 5};
#pragma unroll
        for (int b = 0; b < 6; b++) {
            int k = ks[b], r = rs[b];
            int span = r * (k - 1) + 1;
            int off = (13 - span) / 2;           // center the dilated kernel
            int ai = i - off, aj = j - off;
            if (ai >= 0 && aj >= 0 && (ai % r) == 0 && (aj % r) == 0) {
                int a = ai / r, bb = aj / r;
                if (a < k && bb < k)
                    val += inv[b + 1] * ws[b][c * k * k + a * k + bb];
            }
        }
        v[t] = val;
    }
    __syncthreads();

    if (t < 91) {                       // wpE: i = t/7, k = t%7
        int i = t / 7, k = t % 7;
        float lo = v[i * 13 + 2 * k];   // 2k <= 12
        float hi = (2 * k + 1 < 13) ? v[i * 13 + 2 * k + 1] : 0.f;
        float2 d2 = make_float2(lo, hi);
        g_Wd[c * W_U64_PER_IMG + i * WSTRIDE + k] = *reinterpret_cast<u64*>(&d2);
    } else if (t < 182) {               // wpO: slots 8..14
        int u = t - 91;
        int i = u / 7, k = u % 7;
        float lo = (k == 0) ? 0.f : v[i * 13 + 2 * k - 1];
        float hi = (k == 0) ? v[i * 13] : v[i * 13 + 2 * k];
        float2 d2 = make_float2(lo, hi);
        g_Wd[c * W_U64_PER_IMG + i * WSTRIDE + 8 + k] = *reinterpret_cast<u64*>(&d2);
    } else if (t < 208) {               // zero pad slots 7 and 15
        int u = t - 182;                // 0..25
        int i = u / 2;
        int slot = 7 + (u % 2) * 8;
        g_Wd[c * W_U64_PER_IMG + i * WSTRIDE + slot] = 0ull;
    }
    if (t == 0) {
        float bsum = 0.f;
#pragma unroll
        for (int m = 0; m < 7; m++)
            bsum += beta[m * C_CH + c] - mean[m * C_CH + c] * inv[m];
        g_bias[c] = bsum;
    }
}

// ---------------------------------------------------------------------------
// FFMA2 (PTX-only on sm_103a). Operands are compiler-visible u64 pairs.
// ---------------------------------------------------------------------------
__device__ __forceinline__ u64 pack2(float lo, float hi) {
    float2 tv = make_float2(lo, hi);
    return *reinterpret_cast<u64*>(&tv);
}
__device__ __forceinline__ void fma2(u64& a, u64 x, u64 w) {
    asm("fma.rn.f32x2 %0, %1, %2, %0;" : "+l"(a) : "l"(x), "l"(w));
}

// Load 10 aligned float2 (offsets 0..19 floats) as u64 pair operands.
__device__ __forceinline__ void load10(u64* f, const float* rowptr) {
    const float2* rp = reinterpret_cast<const float2*>(rowptr);
#pragma unroll
    for (int k = 0; k < 10; k++) {
        float2 v = rp[k];                            // LDS.64
        f[k] = *reinterpret_cast<u64*>(&v);
    }
}

// ---------------------------------------------------------------------------
// Fan one loaded input row out to NA accumulator rows.
// acc[a][x] = (even-tap partial, odd-tap partial) of local output x (0..7),
// using weight row (wrow0 - a). No packing: all f[] are aligned pairs.
// ---------------------------------------------------------------------------
template <int NA>
__device__ __forceinline__ void compute_row(const u64* __restrict__ f,
                                            const u64* __restrict__ mw,
                                            int wrow0,
                                            u64 (*acc)[8]) {
#pragma unroll
    for (int a = 0; a < NA; a++) {
        const u64* wr = mw + (wrow0 - a) * WSTRIDE;
        const ulonglong2* e2 = reinterpret_cast<const ulonglong2*>(wr);
        u64 wE[7];
        {
            ulonglong2 t0 = e2[0], t1 = e2[1], t2 = e2[2];   // LDS.128 x3
            wE[0] = t0.x; wE[1] = t0.y; wE[2] = t1.x; wE[3] = t1.y;
            wE[4] = t2.x; wE[5] = t2.y; wE[6] = wr[6];        // LDS.64
        }
#pragma unroll
        for (int e = 0; e < 4; e++) {          // even outputs x = 2e
#pragma unroll
            for (int k = 0; k < 7; k++)
                fma2(acc[a][2 * e], f[e + k], wE[k]);
        }
        const ulonglong2* o2 = reinterpret_cast<const ulonglong2*>(wr + 8);
        u64 wO[7];
        {
            ulonglong2 t0 = o2[0], t1 = o2[1], t2 = o2[2];   // LDS.128 x3
            wO[0] = t0.x; wO[1] = t0.y; wO[2] = t1.x; wO[3] = t1.y;
            wO[4] = t2.x; wO[5] = t2.y; wO[6] = wr[14];       // LDS.64
        }
#pragma unroll
        for (int o = 0; o < 4; o++) {          // odd outputs x = 2o+1
#pragma unroll
            for (int k = 0; k < 7; k++)
                fma2(acc[a][2 * o + 1], f[o + k], wO[k]);
        }
    }
}

template <int NA>
__device__ __forceinline__ void proc_row(const float* __restrict__ rowptr,
                                         const u64* __restrict__ mw,
                                         int wrow0,
                                         u64 (*acc)[8]) {
    u64 f[10];
    load10(f, rowptr);
    compute_row<NA>(f, mw, wrow0, acc);
}

// Horizontal-reduce each output (lo+hi) and store as 2x STG.128 per row.
__device__ __forceinline__ void store_rows(float* obase, int y0, int dfirst,
                                           int nd, const u64 (*acc)[8]) {
    for (int d = 0; d < nd; d++) {
        float o[8];
#pragma unroll
        for (int x = 0; x < 8; x++) {
            float2 v = *reinterpret_cast<const float2*>(&acc[d][x]);
            o[x] = v.x + v.y;
        }
        float4* orow = reinterpret_cast<float4*>(obase + (y0 + dfirst + d) * HW);
        orow[0] = make_float4(o[0], o[1], o[2], o[3]);
        orow[1] = make_float4(o[4], o[5], o[6], o[7]);
    }
}

// ---------------------------------------------------------------------------
// Kernel 2: depthwise 13x13 conv + bias.
// Block = 4 (n,c) images. Per image: 56 threads = 7 x-tiles (8 wide) x 8 ty.
// Thread strip = 8 wide x 7 rows in three passes (d=0-1, 2-3, 4-6).
// Steady loops: unroll 1 + ping-pong row prefetch (f/g).
// ---------------------------------------------------------------------------
extern __shared__ char s_raw[];

__global__ __launch_bounds__(THREADS, 2)
void conv13_kernel(const float* __restrict__ x, float* __restrict__ out) {
    float* s_in = reinterpret_cast<float*>(s_raw);
    u64* s_w = reinterpret_cast<u64*>(s_raw + SMEM_IN_BYTES);

    int t = threadIdx.x;
    int img_l = t / 56;
    int s = t % 56;
    int tx = s % 7, ty = s / 7;
    int x0 = tx * 8;
    int y0 = ty * 7;

    int img = blockIdx.x * IMG_PER_BLK + img_l;   // flat (n*C + c)
    int c = img % C_CH;

    float* my = s_in + img_l * (PH * PH);
    u64* mw = s_w + img_l * W_U64_PER_IMG;
    const float* gx = x + (size_t)img * (HW * HW);

    // Stage merged weight pairs: 208 u64 = 104 ulonglong2 per image (guarded).
    {
        const ulonglong2* src =
            reinterpret_cast<const ulonglong2*>(g_Wd + (size_t)c * W_U64_PER_IMG);
        ulonglong2* dst = reinterpret_cast<ulonglong2*>(mw);
        for (int k = s; k < W_U64_PER_IMG / 2; k += 56)
            dst[k] = __ldg(src + k);
    }

    // Stage input: vector zero-fill padded tile, then coalesced float2
    // interior copy (constant-divisor indexing, no runtime div).
    {
        float4* z = reinterpret_cast<float4*>(my);
        for (int k = s; k < (PH * PH) / 4; k += 56)        // 1156 float4
            z[k] = make_float4(0.f, 0.f, 0.f, 0.f);
    }
    __syncthreads();
    {
        int col2 = s % 28;          // column pair 0..27
        int r0 = s / 28;            // 0 or 1
        const float2* g2 = reinterpret_cast<const float2*>(gx);
#pragma unroll
        for (int k = 0; k < 28; k++) {
            int r = r0 + 2 * k;
            float2 v = __ldg(g2 + r * 28 + col2);
            *reinterpret_cast<float2*>(my + (r + PAD) * PH + PAD + 2 * col2) = v;
        }
    }
    __syncthreads();

    float bb = __ldg(&g_bias[c]);
    u64 biasE = pack2(bb, 0.f);     // bias in even lane; lo+hi adds it once

    const float* rbase = my + y0 * PH + x0;   // padded coords, 8B aligned
    float* obase = out + (size_t)img * (HW * HW) + x0;

    // =================== Pass 1: output rows d = 0..1 (rows 0..13) ==========
    {
        u64 acc[2][8];
#pragma unroll
        for (int a = 0; a < 2; a++)
#pragma unroll
            for (int q = 0; q < 8; q++) acc[a][q] = biasE;

        proc_row<1>(rbase + 0 * PH, mw, 0, &acc[0]);   // ir=0: d0 only
        u64 f[10], g[10];
        load10(f, rbase + 1 * PH);
#pragma unroll 1
        for (int ir = 1; ir < 12; ir += 2) {           // bodies: 1..12
            load10(g, rbase + (ir + 1) * PH);
            compute_row<2>(f, mw, ir, &acc[0]);
            load10(f, rbase + (ir + 2) * PH);          // last: row 13
            compute_row<2>(g, mw, ir + 1, &acc[0]);
        }
        compute_row<1>(f, mw, 12, &acc[1]);            // ir=13: d1 only
        store_rows(obase, y0, 0, 2, acc);
    }

    // =================== Pass 2: output rows d = 2..3 (rows 2..15) ==========
    {
        u64 acc[2][8];
#pragma unroll
        for (int a = 0; a < 2; a++)
#pragma unroll
            for (int q = 0; q < 8; q++) acc[a][q] = biasE;

        proc_row<1>(rbase + 2 * PH, mw, 0, &acc[0]);   // ir=2: d2 only
        u64 f[10], g[10];
        load10(f, rbase + 3 * PH);
#pragma unroll 1
        for (int ir = 3; ir < 14; ir += 2) {           // bodies: 3..14
            load10(g, rbase + (ir + 1) * PH);
            compute_row<2>(f, mw, ir - 2, &acc[0]);
            load10(f, rbase + (ir + 2) * PH);          // last: row 15
            compute_row<2>(g, mw, ir - 1, &acc[0]);
        }
        compute_row<1>(f, mw, 12, &acc[1]);            // ir=15: d3 only
        store_rows(obase, y0, 2, 2, acc);
    }

    // =================== Pass 3: output rows d = 4..6 (rows 4..18) ==========
    {
        u64 acc[3][8];
#pragma unroll
        for (int a = 0; a < 3; a++)
#pragma unroll
            for (int q = 0; q < 8; q++) acc[a][q] = biasE;

        proc_row<1>(rbase + 4 * PH, mw, 0, &acc[0]);   // ir=4: d4
        proc_row<2>(rbase + 5 * PH, mw, 1, &acc[0]);   // ir=5: d4,d5
        u64 f[10], g[10];
        load10(f, rbase + 6 * PH);
#pragma unroll 1
        for (int ir = 6; ir < 15; ir += 2) {           // bodies: 6..15
            load10(g, rbase + (ir + 1) * PH);
            compute_row<3>(f, mw, ir - 4, &acc[0]);
            load10(f, rbase + (ir + 2) * PH);          // last: row 16
            compute_row<3>(g, mw, ir - 3, &acc[0]);
        }
        compute_row<3>(f, mw, 12, &acc[0]);            // ir=16: d4,d5,d6
        proc_row<2>(rbase + 17 * PH, mw, 12, &acc[1]); // ir=17: d5,d6
        proc_row<1>(rbase + 18 * PH, mw, 12, &acc[2]); // ir=18: d6
        store_rows(obase, y0, 4, 3, acc);
    }
}

// ---------------------------------------------------------------------------
extern "C" void kernel_launch(void* const* d_in, const int* in_sizes, int n_in,
                              void* d_out, int out_size) {
    const float* x    = (const float*)d_in[0];
    const float* w_lk = (const float*)d_in[1];
    const float* w_b0 = (const float*)d_in[2];
    const float* w_b1 = (const float*)d_in[3];
    const float* w_b2 = (const float*)d_in[4];
    const float* w_b3 = (const float*)d_in[5];
    const float* w_b4 = (const float*)d_in[6];
    const float* w_b5 = (const float*)d_in[7];
    const float* gam  = (const float*)d_in[8];
    const float* bet  = (const float*)d_in[9];
    const float* mea  = (const float*)d_in[10];
    const float* var  = (const float*)d_in[11];
    float* out = (float*)d_out;

    merge_kernel<<<C_CH, 224>>>(w_lk, w_b0, w_b1, w_b2, w_b3, w_b4, w_b5,
                                gam, bet, mea, var);

    cudaFuncSetAttribute(conv13_kernel,
                         cudaFuncAttributeMaxDynamicSharedMemorySize,
                         SMEM_BYTES);
    int grid = (NB * C_CH) / IMG_PER_BLK;  // 1536
    conv13_kernel<<<grid, THREADS, SMEM_BYTES>>>(x, out);
}